// round 6
// baseline (speedup 1.0000x reference)
#include <cuda_runtime.h>
#include <cstdint>

// Embedding backward (scatter-add), chunked for L2 residency.
//   d_in[0]: grad_output, float32, [B*S, 128]   (B*S = 131072)
//   d_in[1]: indices,     int32,   [B*S]
//   d_out  : float32 [200000, 128]; segment_sum skipping index==0.
//
// Structure: for each table chunk (~51 MB, fits L2):
//   1) zero the chunk with NORMAL stores  -> dirty lines resident in L2
//   2) scatter-add all rows whose index falls in the chunk
//      -> red.global.add.v4.f32 RMWs hit L2-resident lines (no DRAM read)
// Table data then makes exactly ONE DRAM trip (final writeback), instead of
// zero-write + RMW-read + writeback.

static constexpr int D  = 128;
static constexpr int D4 = D / 4;       // 32 float4 per row = one warp
static constexpr int NUM_CHUNKS = 2;   // ~51 MB per chunk, L2 is ~126 MB

// ---------------------------------------------------------------------------
// Zero rows [row_lo, row_hi) with normal (write-allocate) float4 stores.
// ---------------------------------------------------------------------------
__global__ void __launch_bounds__(256) zero_chunk_kernel(float4* __restrict__ out,
                                                         long long f4_lo,
                                                         long long f4_hi) {
    long long i = f4_lo + (long long)blockIdx.x * blockDim.x + threadIdx.x;
    if (i < f4_hi) {
        out[i] = make_float4(0.f, 0.f, 0.f, 0.f);
    }
}

// ---------------------------------------------------------------------------
// Scatter-add rows whose index e satisfies row_lo <= e < row_hi (and e != 0).
// Warp-per-row; lane owns one float4; vector RED.
// ---------------------------------------------------------------------------
__global__ void __launch_bounds__(256) scatter_chunk_kernel(
    const float4* __restrict__ grad,   // [rows, 32] as float4
    const int* __restrict__ indices,   // [rows]
    float* __restrict__ out,           // [V, 128]
    int rows, int row_lo, int row_hi)
{
    int warp = (blockIdx.x * blockDim.x + threadIdx.x) >> 5;
    int lane = threadIdx.x & 31;
    if (warp >= rows) return;

    int e = __ldg(&indices[warp]);
    // Uniform across warp: no divergence. Skip padding and out-of-chunk rows.
    if (e == 0 || e < row_lo || e >= row_hi) return;

    // Evict-first read: keep the 64 MB grad stream out of the live L2 chunk.
    float4 g = __ldcs(&grad[(long long)warp * D4 + lane]);

    float* dst = out + (long long)e * D + lane * 4;
    asm volatile(
        "red.global.add.v4.f32 [%0], {%1, %2, %3, %4};"
        :
        : "l"(dst), "f"(g.x), "f"(g.y), "f"(g.z), "f"(g.w)
        : "memory");
}

// ---------------------------------------------------------------------------
extern "C" void kernel_launch(void* const* d_in, const int* in_sizes, int n_in,
                              void* d_out, int out_size) {
    const float4* grad = (const float4*)d_in[0];
    const int* indices = (const int*)d_in[1];
    float* out         = (float*)d_out;

    const int rows = in_sizes[1];                 // B*S = 131072
    const long long n4 = (long long)out_size / 4; // total output float4s
    const long long V  = (long long)out_size / D; // number of table rows

    const int threads = 256;
    const int scatter_blocks = (rows + (threads / 32) - 1) / (threads / 32);

    long long rows_per_chunk = (V + NUM_CHUNKS - 1) / NUM_CHUNKS;

    for (int c = 0; c < NUM_CHUNKS; ++c) {
        long long row_lo = c * rows_per_chunk;
        long long row_hi = row_lo + rows_per_chunk;
        if (row_hi > V) row_hi = V;
        if (row_lo >= row_hi) break;

        // 1) Zero this chunk (normal stores -> L2-resident dirty lines).
        long long f4_lo = row_lo * D4;
        long long f4_hi = row_hi * D4;
        long long n     = f4_hi - f4_lo;
        int zblocks = (int)((n + threads - 1) / threads);
        zero_chunk_kernel<<<zblocks, threads>>>((float4*)out, f4_lo, f4_hi);

        // 2) Scatter-add all rows targeting this chunk (RMW hits L2).
        scatter_chunk_kernel<<<scatter_blocks, threads>>>(
            grad, indices, out, rows, (int)row_lo, (int)row_hi);
    }
}

// round 7
// speedup vs baseline: 1.2209x; 1.2209x over previous
#include <cuda_runtime.h>
#include <cstdint>

// Embedding backward (scatter-add), chunked for L2 residency + MLP-8 scatter.
//   d_in[0]: grad_output, float32, [B*S, 128]   (B*S = 131072)
//   d_in[1]: indices,     int32,   [B*S]
//   d_out  : float32 [200000, 128]; segment_sum skipping index==0.
//
// Per table chunk (~51 MB, fits L2):
//   1) zero chunk with NORMAL stores  -> dirty lines resident in L2
//   2) scatter-add rows targeting the chunk; red.global.add.v4.f32 RMWs hit
//      L2-resident lines (no DRAM read-allocate — verified in R5 profile).
// R6 change: warp handles 8 rows (batched int4 index load + 8 independent
// grad loads in flight) to convert the latency-bound scatter into a
// bandwidth-bound one.

static constexpr int D   = 128;
static constexpr int D4  = D / 4;      // 32 float4 per row = one warp
static constexpr int RPW = 8;          // rows per warp
static constexpr int NUM_CHUNKS = 2;   // ~51 MB per chunk vs ~126 MB L2

// ---------------------------------------------------------------------------
// Zero float4s [f4_lo, f4_hi) with normal (write-allocate) stores.
// ---------------------------------------------------------------------------
__global__ void __launch_bounds__(256) zero_chunk_kernel(float4* __restrict__ out,
                                                         long long f4_lo,
                                                         long long f4_hi) {
    long long i = f4_lo + (long long)blockIdx.x * blockDim.x + threadIdx.x;
    if (i < f4_hi) {
        out[i] = make_float4(0.f, 0.f, 0.f, 0.f);
    }
}

// ---------------------------------------------------------------------------
// Scatter: each warp owns RPW=8 consecutive rows. Batched index load,
// up to 8 grad loads in flight, then 8 vector REDs.
// ---------------------------------------------------------------------------
__global__ void __launch_bounds__(256) scatter_chunk_kernel(
    const float4* __restrict__ grad,   // [rows, 32] as float4
    const int* __restrict__ indices,   // [rows]
    float* __restrict__ out,           // [V, 128]
    int rows, int row_lo, int row_hi)
{
    int warp = (blockIdx.x * blockDim.x + threadIdx.x) >> 5;
    int lane = threadIdx.x & 31;
    int base = warp * RPW;
    if (base >= rows) return;

    int e[RPW];
    if (base + RPW <= rows) {
        // rows is a multiple of 8 in practice; vector index load (uniform
        // across warp -> L1 broadcast).
        int4 ia = __ldg(reinterpret_cast<const int4*>(indices) + warp * 2);
        int4 ib = __ldg(reinterpret_cast<const int4*>(indices) + warp * 2 + 1);
        e[0]=ia.x; e[1]=ia.y; e[2]=ia.z; e[3]=ia.w;
        e[4]=ib.x; e[5]=ib.y; e[6]=ib.z; e[7]=ib.w;
    } else {
        #pragma unroll
        for (int j = 0; j < RPW; ++j)
            e[j] = (base + j < rows) ? __ldg(&indices[base + j]) : 0;
    }

    // Issue all valid grad loads back-to-back (MLP up to 8). Evict-first so
    // the grad stream doesn't evict the L2-resident table chunk.
    bool   v[RPW];
    float4 g[RPW];
    #pragma unroll
    for (int j = 0; j < RPW; ++j) {
        v[j] = (e[j] != 0) & (e[j] >= row_lo) & (e[j] < row_hi);
        if (v[j])
            g[j] = __ldcs(&grad[(long long)(base + j) * D4 + lane]);
    }

    #pragma unroll
    for (int j = 0; j < RPW; ++j) {
        if (v[j]) {
            float* dst = out + (long long)e[j] * D + lane * 4;
            asm volatile(
                "red.global.add.v4.f32 [%0], {%1, %2, %3, %4};"
                :
                : "l"(dst), "f"(g[j].x), "f"(g[j].y), "f"(g[j].z), "f"(g[j].w)
                : "memory");
        }
    }
}

// ---------------------------------------------------------------------------
extern "C" void kernel_launch(void* const* d_in, const int* in_sizes, int n_in,
                              void* d_out, int out_size) {
    const float4* grad = (const float4*)d_in[0];
    const int* indices = (const int*)d_in[1];
    float* out         = (float*)d_out;

    const int rows = in_sizes[1];                  // B*S = 131072
    const long long V = (long long)out_size / D;   // table rows = 200000

    const int threads = 256;                       // 8 warps/CTA
    const int rows_per_block = (threads / 32) * RPW;  // 64
    const int scatter_blocks = (rows + rows_per_block - 1) / rows_per_block;

    long long rows_per_chunk = (V + NUM_CHUNKS - 1) / NUM_CHUNKS;

    for (int c = 0; c < NUM_CHUNKS; ++c) {
        long long row_lo = c * rows_per_chunk;
        long long row_hi = row_lo + rows_per_chunk;
        if (row_hi > V) row_hi = V;
        if (row_lo >= row_hi) break;

        // 1) Zero this chunk into L2.
        long long f4_lo = row_lo * D4;
        long long f4_hi = row_hi * D4;
        long long n     = f4_hi - f4_lo;
        int zblocks = (int)((n + threads - 1) / threads);
        zero_chunk_kernel<<<zblocks, threads>>>((float4*)out, f4_lo, f4_hi);

        // 2) Scatter-add into the L2-resident chunk.
        scatter_chunk_kernel<<<scatter_blocks, threads>>>(
            grad, indices, out, rows, (int)row_lo, (int)row_hi);
    }
}